// round 1
// baseline (speedup 1.0000x reference)
#include <cuda_runtime.h>
#include <cstdint>
#include <cstddef>

#define BB 8
#define SS 2048
#define DD 1024
// DC == DD == 1024, scale = 1/sqrt(1024) = 1/32

// ---------------- scratch (static device globals; no allocation) ----------------
__device__ int   g_labels[BB * SS];
__device__ int   g_chunk_start[BB * SS];
__device__ int   g_chunk_len[BB * SS];
__device__ int   g_nchunks[BB];
__device__ float g_chunk_emb[(size_t)BB * SS * DD];   // 64 MB
__device__ float g_q[(size_t)BB * SS * DD];           // 64 MB
__device__ float g_k[(size_t)BB * SS * DD];           // 64 MB
__device__ float g_v[(size_t)BB * SS * DD];           // 64 MB
__device__ float g_att[(size_t)BB * SS * DD];         // 64 MB
__device__ float g_scores[(size_t)BB * SS * SS];      // 128 MB

// ---------------- 1) labels = argmax(h @ W_lab + b_lab) ----------------
// one warp per token; W_lab is (D,4) row-major -> row k is a float4
__global__ void label_kernel(const float* __restrict__ h,
                             const float* __restrict__ Wlab,
                             const float* __restrict__ blab) {
    int tok  = blockIdx.x * (blockDim.x >> 5) + (threadIdx.x >> 5);
    int lane = threadIdx.x & 31;
    const float* hr = h + (size_t)tok * DD;
    float a0 = 0.f, a1 = 0.f, a2 = 0.f, a3 = 0.f;
    for (int k = lane; k < DD; k += 32) {
        float hv = hr[k];
        float4 w = *(const float4*)(Wlab + k * 4);
        a0 += hv * w.x; a1 += hv * w.y; a2 += hv * w.z; a3 += hv * w.w;
    }
    #pragma unroll
    for (int o = 16; o; o >>= 1) {
        a0 += __shfl_down_sync(0xffffffffu, a0, o);
        a1 += __shfl_down_sync(0xffffffffu, a1, o);
        a2 += __shfl_down_sync(0xffffffffu, a2, o);
        a3 += __shfl_down_sync(0xffffffffu, a3, o);
    }
    if (lane == 0) {
        float lg[4] = { a0 + blab[0], a1 + blab[1], a2 + blab[2], a3 + blab[3] };
        int best = 0; float bv = lg[0];
        #pragma unroll
        for (int j = 1; j < 4; j++) if (lg[j] > bv) { bv = lg[j]; best = j; }  // first-max tie-break
        g_labels[tok] = best;
    }
}

// ---------------- 2) sequential BIOS chunk scan (per batch row) ----------------
__global__ void scan_kernel() {
    __shared__ int lab[SS];
    int b = blockIdx.x;
    for (int s = threadIdx.x; s < SS; s += blockDim.x) lab[s] = g_labels[b * SS + s];
    __syncthreads();
    if (threadIdx.x == 0) {
        int* cs = g_chunk_start + b * SS;
        int* cl = g_chunk_len   + b * SS;
        bool open = false; int c = -1;
        for (int s = 0; s < SS; s++) {
            int l = lab[s];
            bool cont = (l == 1) && open;
            open = (l == 0) || cont;
            if (!cont) {
                if (c >= 0) cl[c] = s - cs[c];
                c++; cs[c] = s;
            }
        }
        cl[c] = SS - cs[c];
        g_nchunks[b] = c + 1;
    }
}

// ---------------- 3) per-chunk mean over contiguous token ranges ----------------
// grid (S, B); block 256; each thread owns 4 contiguous d-columns (float4)
__global__ void chunk_mean_kernel(const float* __restrict__ h) {
    int b = blockIdx.y, c = blockIdx.x;
    float* out = g_chunk_emb + ((size_t)b * SS + c) * DD;
    int d = threadIdx.x * 4;
    int nc = g_nchunks[b];
    if (c >= nc) {  // padded chunk rows must be deterministically zero
        *(float4*)(out + d) = make_float4(0.f, 0.f, 0.f, 0.f);
        return;
    }
    int st  = g_chunk_start[b * SS + c];
    int len = g_chunk_len[b * SS + c];
    const float* base = h + ((size_t)b * SS + st) * DD + d;
    float4 acc = make_float4(0.f, 0.f, 0.f, 0.f);
    for (int t = 0; t < len; t++) {
        float4 v = *(const float4*)(base + (size_t)t * DD);
        acc.x += v.x; acc.y += v.y; acc.z += v.z; acc.w += v.w;
    }
    float lf = (float)len;
    acc.x /= lf; acc.y /= lf; acc.z /= lf; acc.w /= lf;
    *(float4*)(out + d) = acc;
}

// ---------------- 4) tiled SGEMM: C = alpha * A @ op(B) + bias ----------------
// A: (M,K) row-major. TRANSB ? B:(N,K) row-major : B:(K,N) row-major. C:(M,N).
// BM=BN=128, BK=16, 256 threads, 8x8 microtile. All dims multiples of 128/16.
template <bool TRANSB>
__global__ __launch_bounds__(256)
void gemm_kernel(const float* __restrict__ A, const float* __restrict__ Bm,
                 const float* __restrict__ bias, float* __restrict__ C,
                 int M, int N, int K,
                 long long sA, long long sB, long long sC, float alpha) {
    constexpr int BM = 128, BN = 128, BK = 16;
    __shared__ float As[BK][BM];
    __shared__ float Bs[BK][BN];

    int bz = blockIdx.z;
    A  += (size_t)bz * sA;
    Bm += (size_t)bz * sB;
    C  += (size_t)bz * sC;

    int bm = blockIdx.y * BM, bn = blockIdx.x * BN;
    int tid = threadIdx.x;
    int tx = tid & 15, ty = tid >> 4;   // 16x16 thread grid

    float acc[8][8];
    #pragma unroll
    for (int i = 0; i < 8; i++)
        #pragma unroll
        for (int j = 0; j < 8; j++) acc[i][j] = 0.f;

    for (int k0 = 0; k0 < K; k0 += BK) {
        // load A tile (BM x BK) -> As transposed [BK][BM]
        #pragma unroll
        for (int i = 0; i < 2; i++) {
            int r  = (tid >> 2) + 64 * i;
            int c4 = (tid & 3);
            float4 v = *(const float4*)(A + (size_t)(bm + r) * K + k0 + c4 * 4);
            As[c4 * 4 + 0][r] = v.x; As[c4 * 4 + 1][r] = v.y;
            As[c4 * 4 + 2][r] = v.z; As[c4 * 4 + 3][r] = v.w;
        }
        // load B tile
        if (TRANSB) {
            #pragma unroll
            for (int i = 0; i < 2; i++) {
                int r  = (tid >> 2) + 64 * i;
                int c4 = (tid & 3);
                float4 v = *(const float4*)(Bm + (size_t)(bn + r) * K + k0 + c4 * 4);
                Bs[c4 * 4 + 0][r] = v.x; Bs[c4 * 4 + 1][r] = v.y;
                Bs[c4 * 4 + 2][r] = v.z; Bs[c4 * 4 + 3][r] = v.w;
            }
        } else {
            #pragma unroll
            for (int i = 0; i < 2; i++) {
                int r  = (tid >> 5) + 8 * i;
                int c4 = (tid & 31);
                float4 v = *(const float4*)(Bm + (size_t)(k0 + r) * N + bn + c4 * 4);
                *(float4*)&Bs[r][c4 * 4] = v;
            }
        }
        __syncthreads();

        #pragma unroll
        for (int kk = 0; kk < BK; kk++) {
            float ar[8], br[8];
            #pragma unroll
            for (int i = 0; i < 8; i++) ar[i] = As[kk][ty * 8 + i];
            #pragma unroll
            for (int j = 0; j < 8; j++) br[j] = Bs[kk][tx * 8 + j];
            #pragma unroll
            for (int i = 0; i < 8; i++)
                #pragma unroll
                for (int j = 0; j < 8; j++) acc[i][j] += ar[i] * br[j];
        }
        __syncthreads();
    }

    #pragma unroll
    for (int i = 0; i < 8; i++) {
        size_t row = (size_t)(bm + ty * 8 + i);
        #pragma unroll
        for (int j4 = 0; j4 < 2; j4++) {
            int col = bn + tx * 8 + j4 * 4;
            float4 o;
            o.x = acc[i][j4 * 4 + 0] * alpha;
            o.y = acc[i][j4 * 4 + 1] * alpha;
            o.z = acc[i][j4 * 4 + 2] * alpha;
            o.w = acc[i][j4 * 4 + 3] * alpha;
            if (bias) {
                float4 bv = *(const float4*)(bias + col);
                o.x += bv.x; o.y += bv.y; o.z += bv.z; o.w += bv.w;
            }
            *(float4*)(C + row * N + col) = o;
        }
    }
}

// ---------------- 5) masked row softmax over chunk axis ----------------
// one block (256 thr) per (b,s) row of g_scores; 2048 cols -> 8 per thread
__global__ void softmax_kernel() {
    __shared__ float red[8];
    int row = blockIdx.x;
    int b = row >> 11;               // / SS
    int nc = g_nchunks[b];
    float* sc = g_scores + (size_t)row * SS;

    const float NEG_INF = __int_as_float(0xff800000);
    float x[8];
    float m = NEG_INF;
    #pragma unroll
    for (int i = 0; i < 8; i++) {
        int c = threadIdx.x + i * 256;
        x[i] = (c < nc) ? sc[c] : NEG_INF;
        m = fmaxf(m, x[i]);
    }
    #pragma unroll
    for (int o = 16; o; o >>= 1) m = fmaxf(m, __shfl_xor_sync(0xffffffffu, m, o));
    if ((threadIdx.x & 31) == 0) red[threadIdx.x >> 5] = m;
    __syncthreads();
    m = red[0];
    #pragma unroll
    for (int i = 1; i < 8; i++) m = fmaxf(m, red[i]);
    __syncthreads();

    float s = 0.f;
    #pragma unroll
    for (int i = 0; i < 8; i++) {
        int c = threadIdx.x + i * 256;
        x[i] = (c < nc) ? expf(x[i] - m) : 0.f;
        s += x[i];
    }
    #pragma unroll
    for (int o = 16; o; o >>= 1) s += __shfl_xor_sync(0xffffffffu, s, o);
    if ((threadIdx.x & 31) == 0) red[threadIdx.x >> 5] = s;
    __syncthreads();
    s = 0.f;
    #pragma unroll
    for (int i = 0; i < 8; i++) s += red[i];
    float inv = 1.f / s;

    #pragma unroll
    for (int i = 0; i < 8; i++) {
        int c = threadIdx.x + i * 256;
        sc[c] = x[i] * inv;
    }
}

// ---------------- host side ----------------
static void launch_gemm(bool transB, const float* A, const float* Bm, const float* bias,
                        float* C, int M, int N, int K,
                        long long sA, long long sB, long long sC, int batch, float alpha) {
    dim3 grid(N / 128, M / 128, batch), block(256);
    if (transB)
        gemm_kernel<true><<<grid, block>>>(A, Bm, bias, C, M, N, K, sA, sB, sC, alpha);
    else
        gemm_kernel<false><<<grid, block>>>(A, Bm, bias, C, M, N, K, sA, sB, sC, alpha);
}

extern "C" void kernel_launch(void* const* d_in, const int* in_sizes, int n_in,
                              void* d_out, int out_size) {
    (void)in_sizes; (void)n_in; (void)out_size;
    const float* h    = (const float*)d_in[0];
    const float* Wlab = (const float*)d_in[1];
    const float* blab = (const float*)d_in[2];
    const float* Wq   = (const float*)d_in[3];
    const float* bq   = (const float*)d_in[4];
    const float* Wk   = (const float*)d_in[5];
    const float* bk   = (const float*)d_in[6];
    const float* Wv   = (const float*)d_in[7];
    const float* bv   = (const float*)d_in[8];
    const float* Wo   = (const float*)d_in[9];
    const float* bo   = (const float*)d_in[10];
    float* out = (float*)d_out;

    float *ce, *q, *k, *v, *att, *sc;
    cudaGetSymbolAddress((void**)&ce,  g_chunk_emb);
    cudaGetSymbolAddress((void**)&q,   g_q);
    cudaGetSymbolAddress((void**)&k,   g_k);
    cudaGetSymbolAddress((void**)&v,   g_v);
    cudaGetSymbolAddress((void**)&att, g_att);
    cudaGetSymbolAddress((void**)&sc,  g_scores);

    const int M = BB * SS;                      // 16384
    const long long sQ = (long long)SS * DD;    // per-batch q/k/v stride
    const long long sS = (long long)SS * SS;    // per-batch scores stride

    label_kernel<<<M / 8, 256>>>(h, Wlab, blab);
    scan_kernel<<<BB, 256>>>();
    chunk_mean_kernel<<<dim3(SS, BB), 256>>>(h);

    launch_gemm(false, h,  Wq, bq, q, M, DD, DD, 0, 0, 0, 1, 1.f);   // q = h@Wq + bq
    launch_gemm(false, ce, Wk, bk, k, M, DD, DD, 0, 0, 0, 1, 1.f);   // k = ce@Wk + bk
    launch_gemm(false, ce, Wv, bv, v, M, DD, DD, 0, 0, 0, 1, 1.f);   // v = ce@Wv + bv

    // scores[b] = (q[b] @ k[b]^T) / 32   (NT, batched)
    launch_gemm(true, q, k, nullptr, sc, SS, SS, DD, sQ, sQ, sS, BB, 0.03125f);

    softmax_kernel<<<M, 256>>>();

    // attended[b] = attn[b] @ v[b]       (NN, batched; masked cols are exactly 0)
    launch_gemm(false, sc, v, nullptr, att, SS, DD, SS, sS, sQ, sQ, BB, 1.f);

    launch_gemm(false, att, Wo, bo, out, M, DD, DD, 0, 0, 0, 1, 1.f); // out = att@Wo + bo
}